// round 1
// baseline (speedup 1.0000x reference)
#include <cuda_runtime.h>
#include <cuda_bf16.h>
#include <math.h>

#define LO 3072
#define LC 1024
#define LT 4096   // LO + LC
#define DM 1024   // model dim
#define NH 16
#define DH 64
#define MH 4096

// ---------------- scratch (device globals; no allocation allowed) ----------------
__device__ float g_mod[12 * DM];          // [2 streams][6 chunks][1024]
__device__ float g_xm[LT * DM];           // modulated LN output (obs rows 0..LO-1, cond at LO)
__device__ float g_qkv[LT * 3 * DM];      // raw qkv (obs rows at 0, cond rows at LO*3*DM)
__device__ float g_q[NH * LT * DH];       // [h][global_l][dh], cond tokens first (l<LC)
__device__ float g_k[NH * LT * DH];
__device__ float g_v[NH * LT * DH];
__device__ float g_attn[LT * DM];         // attention out, (L, H*Dh), global l order
__device__ float g_h[LT * MH];            // mlp hidden (obs at 0, cond at LO*MH)

// ---------------- modulation: silu(vec) @ mod_w + mod_b ----------------
__global__ void mod_kernel(const float* __restrict__ vec,
                           const float* __restrict__ ow, const float* __restrict__ ob,
                           const float* __restrict__ cw, const float* __restrict__ cb) {
    __shared__ float sv[DM];
    int tid = threadIdx.x;
    for (int i = tid; i < DM; i += 256) {
        float v = vec[i];
        sv[i] = v / (1.0f + expf(-v));
    }
    __syncthreads();
    int j = blockIdx.x * 256 + tid;          // 0 .. 12287
    int stream = j / (6 * DM);
    int jj = j % (6 * DM);
    const float* w = stream ? cw : ow;
    const float* b = stream ? cb : ob;
    float acc = 0.0f;
    for (int i = 0; i < DM; i++)
        acc += sv[i] * w[(size_t)i * (6 * DM) + jj];
    g_mod[stream * 6 * DM + jj] = acc + b[jj];
}

// ---------------- layernorm + modulation: (1+scale)*LN(x) + shift ----------------
__global__ void ln_mod_kernel(const float* __restrict__ x, float* __restrict__ y,
                              int stream, int shiftc, int scalec) {
    int row = blockIdx.x;
    int tid = threadIdx.x;
    const float* xr = x + (size_t)row * DM;
    __shared__ float r1[256], r2[256];
    float s = 0.0f, ss = 0.0f;
    for (int c = tid; c < DM; c += 256) {
        float v = xr[c];
        s += v; ss += v * v;
    }
    r1[tid] = s; r2[tid] = ss;
    __syncthreads();
    for (int st = 128; st > 0; st >>= 1) {
        if (tid < st) { r1[tid] += r1[tid + st]; r2[tid] += r2[tid + st]; }
        __syncthreads();
    }
    float mean = r1[0] * (1.0f / DM);
    float var = r2[0] * (1.0f / DM) - mean * mean;
    float inv = rsqrtf(var + 1e-6f);
    const float* sh = g_mod + (stream * 6 + shiftc) * DM;
    const float* sc = g_mod + (stream * 6 + scalec) * DM;
    float* yr = y + (size_t)row * DM;
    for (int c = tid; c < DM; c += 256) {
        yr[c] = (xr[c] - mean) * inv * (1.0f + sc[c]) + sh[c];
    }
}

// ---------------- generic SGEMM: C = epilogue(A@B) ----------------
// mode 0: C = AB (+bias)        mode 1: C = resid + gate*(AB + bias)
// mode 2: C = gelu_tanh(AB + bias)
__global__ __launch_bounds__(256) void sgemm_kernel(
    const float* __restrict__ A, const float* __restrict__ B, float* __restrict__ C,
    int M, int N, int K,
    const float* __restrict__ bias, const float* __restrict__ resid,
    int gidx, int mode) {
    __shared__ float As[16][128];
    __shared__ float Bs[16][128];
    int tid = threadIdx.x;
    int tx = tid & 15, ty = tid >> 4;
    int row0 = blockIdx.y * 128, col0 = blockIdx.x * 128;
    float acc[8][8];
#pragma unroll
    for (int i = 0; i < 8; i++)
#pragma unroll
        for (int j = 0; j < 8; j++) acc[i][j] = 0.0f;

    for (int k0 = 0; k0 < K; k0 += 16) {
#pragma unroll
        for (int i = 0; i < 2; i++) {
            int idx = tid + i * 256;           // 0..511 float4 slots
            int r = idx >> 2, c4 = (idx & 3) << 2;
            float4 v = *(const float4*)&A[(size_t)(row0 + r) * K + k0 + c4];
            As[c4 + 0][r] = v.x; As[c4 + 1][r] = v.y;
            As[c4 + 2][r] = v.z; As[c4 + 3][r] = v.w;
        }
#pragma unroll
        for (int i = 0; i < 2; i++) {
            int idx = tid + i * 256;
            int r = idx >> 5, c4 = (idx & 31) << 2;
            *(float4*)&Bs[r][c4] = *(const float4*)&B[(size_t)(k0 + r) * N + col0 + c4];
        }
        __syncthreads();
#pragma unroll
        for (int k = 0; k < 16; k++) {
            float a[8], b[8];
#pragma unroll
            for (int i = 0; i < 8; i++) a[i] = As[k][ty * 8 + i];
#pragma unroll
            for (int j = 0; j < 8; j++) b[j] = Bs[k][tx * 8 + j];
#pragma unroll
            for (int i = 0; i < 8; i++)
#pragma unroll
                for (int j = 0; j < 8; j++) acc[i][j] += a[i] * b[j];
        }
        __syncthreads();
    }

    const float* gate = (gidx >= 0) ? (g_mod + gidx * DM) : nullptr;
#pragma unroll
    for (int i = 0; i < 8; i++) {
        int r = row0 + ty * 8 + i;
#pragma unroll
        for (int j = 0; j < 8; j++) {
            int c = col0 + tx * 8 + j;
            float v = acc[i][j];
            if (bias) v += bias[c];
            if (mode == 1) {
                v = resid[(size_t)r * N + c] + gate[c] * v;
            } else if (mode == 2) {
                float t = v;
                v = 0.5f * t * (1.0f + tanhf(0.7978845608f * (t + 0.044715f * t * t * t)));
            }
            C[(size_t)r * N + c] = v;
        }
    }
}

// ---------------- qkv post: rmsnorm(q,k) + rope, scatter to [h][l][dh] ----------------
__global__ void qkv_post_kernel(const float* __restrict__ pe,
                                const float* __restrict__ oqs, const float* __restrict__ oks,
                                const float* __restrict__ cqs, const float* __restrict__ cks) {
    int gl = blockIdx.x;      // global token (cond first)
    int h = blockIdx.y;
    int d = threadIdx.x;      // 0..63
    bool is_cond = gl < LC;
    const float* src = is_cond ? (g_qkv + (size_t)LO * 3 * DM + (size_t)gl * 3 * DM)
                               : (g_qkv + (size_t)(gl - LC) * 3 * DM);
    const float* qs = is_cond ? cqs : oqs;
    const float* ks = is_cond ? cks : oks;
    float qv = src[h * DH + d];
    float kv = src[DM + h * DH + d];
    float vv = src[2 * DM + h * DH + d];
    float qss = qv * qv, kss = kv * kv;
#pragma unroll
    for (int off = 16; off > 0; off >>= 1) {
        qss += __shfl_xor_sync(0xffffffffu, qss, off);
        kss += __shfl_xor_sync(0xffffffffu, kss, off);
    }
    __shared__ float red[4];
    int w = d >> 5;
    if ((d & 31) == 0) { red[w] = qss; red[2 + w] = kss; }
    __syncthreads();
    qss = red[0] + red[1];
    kss = red[2] + red[3];
    float qn = qv * rsqrtf(qss * (1.0f / DH) + 1e-6f) * qs[d];
    float kn = kv * rsqrtf(kss * (1.0f / DH) + 1e-6f) * ks[d];
    __shared__ float sq[DH], sk[DH];
    sq[d] = qn; sk[d] = kn;
    __syncthreads();
    int p = d >> 1, j = d & 1;
    const float* pp = pe + (((size_t)gl * 32 + p) * 2 + j) * 2;
    float q0 = sq[2 * p], q1 = sq[2 * p + 1];
    float k0 = sk[2 * p], k1 = sk[2 * p + 1];
    float qo = pp[0] * q0 + pp[1] * q1;
    float ko = pp[0] * k0 + pp[1] * k1;
    size_t oidx = ((size_t)h * LT + gl) * DH + d;
    g_q[oidx] = qo;
    g_k[oidx] = ko;
    g_v[oidx] = vv;
}

// ---------------- attention: flash-style, 128 q-rows per block ----------------
__global__ __launch_bounds__(128) void attn_kernel() {
    int h = blockIdx.x;
    int tid = threadIdx.x;
    int qr = blockIdx.y * 128 + tid;
    const float* qp = g_q + ((size_t)h * LT + qr) * DH;
    float q[DH];
#pragma unroll
    for (int d = 0; d < DH; d++) q[d] = qp[d] * 0.125f;  // 1/sqrt(64)
    float o[DH];
#pragma unroll
    for (int d = 0; d < DH; d++) o[d] = 0.0f;
    float m = -1e30f, l = 0.0f;

    __shared__ float Ks[32 * DH];
    __shared__ float Vs[32 * DH];
    const float* kb = g_k + (size_t)h * LT * DH;
    const float* vb = g_v + (size_t)h * LT * DH;

    for (int kt = 0; kt < LT; kt += 32) {
        __syncthreads();
#pragma unroll
        for (int i = 0; i < 4; i++) {
            int idx = tid + i * 128;   // 512 float4 slots
            ((float4*)Ks)[idx] = ((const float4*)(kb + (size_t)kt * DH))[idx];
            ((float4*)Vs)[idx] = ((const float4*)(vb + (size_t)kt * DH))[idx];
        }
        __syncthreads();
        float s[32];
        float tmax = -1e30f;
#pragma unroll
        for (int j = 0; j < 32; j++) {
            float acc = 0.0f;
#pragma unroll
            for (int d = 0; d < DH; d++) acc += q[d] * Ks[j * DH + d];
            s[j] = acc;
            tmax = fmaxf(tmax, acc);
        }
        float mn = fmaxf(m, tmax);
        float corr = __expf(m - mn);
        l *= corr;
#pragma unroll
        for (int d = 0; d < DH; d++) o[d] *= corr;
#pragma unroll
        for (int j = 0; j < 32; j++) {
            float p = __expf(s[j] - mn);
            l += p;
#pragma unroll
            for (int d = 0; d < DH; d++) o[d] += p * Vs[j * DH + d];
        }
        m = mn;
    }
    float inv = 1.0f / l;
    float* outp = g_attn + (size_t)qr * DM + h * DH;
#pragma unroll
    for (int d = 0; d < DH; d++) outp[d] = o[d] * inv;
}

// ---------------- launch ----------------
extern "C" void kernel_launch(void* const* d_in, const int* in_sizes, int n_in,
                              void* d_out, int out_size) {
    const float* obs   = (const float*)d_in[0];
    const float* cond  = (const float*)d_in[1];
    const float* vec   = (const float*)d_in[2];
    const float* pe    = (const float*)d_in[3];
    const float* o_mod_w = (const float*)d_in[4];
    const float* o_mod_b = (const float*)d_in[5];
    const float* o_qkv_w = (const float*)d_in[6];
    const float* o_q_s   = (const float*)d_in[7];
    const float* o_k_s   = (const float*)d_in[8];
    const float* o_proj_w = (const float*)d_in[9];
    const float* o_proj_b = (const float*)d_in[10];
    const float* o_mlp_w1 = (const float*)d_in[11];
    const float* o_mlp_b1 = (const float*)d_in[12];
    const float* o_mlp_w2 = (const float*)d_in[13];
    const float* o_mlp_b2 = (const float*)d_in[14];
    const float* c_mod_w = (const float*)d_in[15];
    const float* c_mod_b = (const float*)d_in[16];
    const float* c_qkv_w = (const float*)d_in[17];
    const float* c_q_s   = (const float*)d_in[18];
    const float* c_k_s   = (const float*)d_in[19];
    const float* c_proj_w = (const float*)d_in[20];
    const float* c_proj_b = (const float*)d_in[21];
    const float* c_mlp_w1 = (const float*)d_in[22];
    const float* c_mlp_b1 = (const float*)d_in[23];
    const float* c_mlp_w2 = (const float*)d_in[24];
    const float* c_mlp_b2 = (const float*)d_in[25];

    float* out = (float*)d_out;
    float* out_obs = out;                 // rows 0..LO-1
    float* out_cond = out + (size_t)LO * DM;

    float *p_xm, *p_qkv, *p_attn, *p_h;
    cudaGetSymbolAddress((void**)&p_xm, g_xm);
    cudaGetSymbolAddress((void**)&p_qkv, g_qkv);
    cudaGetSymbolAddress((void**)&p_attn, g_attn);
    cudaGetSymbolAddress((void**)&p_h, g_h);

    // 1. modulation vectors
    mod_kernel<<<48, 256>>>(vec, o_mod_w, o_mod_b, c_mod_w, c_mod_b);

    // 2. LN + mod (chunks: 0=shift1, 1=scale1)
    ln_mod_kernel<<<LO, 256>>>(obs, p_xm, 0, 0, 1);
    ln_mod_kernel<<<LC, 256>>>(cond, p_xm + (size_t)LO * DM, 1, 0, 1);

    // 3. qkv GEMMs (no bias)
    {
        dim3 g(3 * DM / 128, LO / 128);
        sgemm_kernel<<<g, 256>>>(p_xm, o_qkv_w, p_qkv, LO, 3 * DM, DM, nullptr, nullptr, -1, 0);
    }
    {
        dim3 g(3 * DM / 128, LC / 128);
        sgemm_kernel<<<g, 256>>>(p_xm + (size_t)LO * DM, c_qkv_w, p_qkv + (size_t)LO * 3 * DM,
                                 LC, 3 * DM, DM, nullptr, nullptr, -1, 0);
    }

    // 4. rmsnorm + rope + scatter
    {
        dim3 g(LT, NH);
        qkv_post_kernel<<<g, 64>>>(pe, o_q_s, o_k_s, c_q_s, c_k_s);
    }

    // 5. attention
    {
        dim3 g(NH, LT / 128);
        attn_kernel<<<g, 128>>>();
    }

    // 6. proj + gated residual (gate1 = chunk 2)
    {
        dim3 g(DM / 128, LO / 128);
        sgemm_kernel<<<g, 256>>>(p_attn + (size_t)LC * DM, o_proj_w, out_obs,
                                 LO, DM, DM, o_proj_b, obs, 0 * 6 + 2, 1);
    }
    {
        dim3 g(DM / 128, LC / 128);
        sgemm_kernel<<<g, 256>>>(p_attn, c_proj_w, out_cond,
                                 LC, DM, DM, c_proj_b, cond, 1 * 6 + 2, 1);
    }

    // 7. LN2 + mod (chunks: 3=shift2, 4=scale2)
    ln_mod_kernel<<<LO, 256>>>(out_obs, p_xm, 0, 3, 4);
    ln_mod_kernel<<<LC, 256>>>(out_cond, p_xm + (size_t)LO * DM, 1, 3, 4);

    // 8. mlp1 + gelu
    {
        dim3 g(MH / 128, LO / 128);
        sgemm_kernel<<<g, 256>>>(p_xm, o_mlp_w1, p_h, LO, MH, DM, o_mlp_b1, nullptr, -1, 2);
    }
    {
        dim3 g(MH / 128, LC / 128);
        sgemm_kernel<<<g, 256>>>(p_xm + (size_t)LO * DM, c_mlp_w1, p_h + (size_t)LO * MH,
                                 LC, MH, DM, c_mlp_b1, nullptr, -1, 2);
    }

    // 9. mlp2 + gated residual (gate2 = chunk 5), in-place residual on d_out
    {
        dim3 g(DM / 128, LO / 128);
        sgemm_kernel<<<g, 256>>>(p_h, o_mlp_w2, out_obs, LO, DM, MH, o_mlp_b2, out_obs, 0 * 6 + 5, 1);
    }
    {
        dim3 g(DM / 128, LC / 128);
        sgemm_kernel<<<g, 256>>>(p_h + (size_t)LO * MH, c_mlp_w2, out_cond,
                                 LC, DM, MH, c_mlp_b2, out_cond, 1 * 6 + 5, 1);
    }
}

// round 2
// speedup vs baseline: 1.6383x; 1.6383x over previous
#include <cuda_runtime.h>
#include <cuda_bf16.h>
#include <math.h>

#define LO 3072
#define LC 1024
#define LT 4096   // LO + LC
#define DM 1024   // model dim
#define NH 16
#define DH 64
#define MH 4096

// ---------------- scratch (device globals; no allocation allowed) ----------------
__device__ float g_mod[12 * DM];          // [2 streams][6 chunks][1024]
__device__ float g_xm[LT * DM];           // modulated LN output (obs rows 0..LO-1, cond at LO)
__device__ float g_qkv[LT * 3 * DM];      // raw qkv (obs rows at 0, cond rows at LO*3*DM)
__device__ float g_q[NH * LT * DH];       // [h][global_l][dh], cond tokens first (l<LC)
__device__ float g_k[NH * LT * DH];
__device__ float g_v[NH * LT * DH];
__device__ float g_attn[LT * DM];         // attention out, (L, H*Dh), global l order
__device__ float g_h[LT * MH];            // mlp hidden (obs at 0, cond at LO*MH)

// ---------------- helpers ----------------
__device__ __forceinline__ unsigned f2tf(float f) {
    unsigned u;
    asm("cvt.rna.tf32.f32 %0, %1;" : "=r"(u) : "f"(f));
    return u;
}

__device__ __forceinline__ void mma_tf32(float d[4], const unsigned a[4], const unsigned b[2]) {
    asm volatile(
        "mma.sync.aligned.m16n8k8.row.col.f32.tf32.tf32.f32 "
        "{%0,%1,%2,%3}, {%4,%5,%6,%7}, {%8,%9}, {%0,%1,%2,%3};"
        : "+f"(d[0]), "+f"(d[1]), "+f"(d[2]), "+f"(d[3])
        : "r"(a[0]), "r"(a[1]), "r"(a[2]), "r"(a[3]), "r"(b[0]), "r"(b[1]));
}

// ---------------- modulation: silu(vec) @ mod_w + mod_b ----------------
__global__ void mod_kernel(const float* __restrict__ vec,
                           const float* __restrict__ ow, const float* __restrict__ ob,
                           const float* __restrict__ cw, const float* __restrict__ cb) {
    __shared__ float sv[DM];
    int tid = threadIdx.x;
    for (int i = tid; i < DM; i += 256) {
        float v = vec[i];
        sv[i] = v / (1.0f + expf(-v));
    }
    __syncthreads();
    int j = blockIdx.x * 256 + tid;          // 0 .. 12287
    int stream = j / (6 * DM);
    int jj = j % (6 * DM);
    const float* w = stream ? cw : ow;
    const float* b = stream ? cb : ob;
    float acc = 0.0f;
    for (int i = 0; i < DM; i++)
        acc += sv[i] * w[(size_t)i * (6 * DM) + jj];
    g_mod[stream * 6 * DM + jj] = acc + b[jj];
}

// ---------------- layernorm + modulation: (1+scale)*LN(x) + shift ----------------
__global__ void ln_mod_kernel(const float* __restrict__ x, float* __restrict__ y,
                              int stream, int shiftc, int scalec) {
    int row = blockIdx.x;
    int tid = threadIdx.x;
    const float* xr = x + (size_t)row * DM;
    __shared__ float r1[256], r2[256];
    float s = 0.0f, ss = 0.0f;
    for (int c = tid; c < DM; c += 256) {
        float v = xr[c];
        s += v; ss += v * v;
    }
    r1[tid] = s; r2[tid] = ss;
    __syncthreads();
    for (int st = 128; st > 0; st >>= 1) {
        if (tid < st) { r1[tid] += r1[tid + st]; r2[tid] += r2[tid + st]; }
        __syncthreads();
    }
    float mean = r1[0] * (1.0f / DM);
    float var = r2[0] * (1.0f / DM) - mean * mean;
    float inv = rsqrtf(var + 1e-6f);
    const float* sh = g_mod + (stream * 6 + shiftc) * DM;
    const float* sc = g_mod + (stream * 6 + scalec) * DM;
    float* yr = y + (size_t)row * DM;
    for (int c = tid; c < DM; c += 256) {
        yr[c] = (xr[c] - mean) * inv * (1.0f + sc[c]) + sh[c];
    }
}

// ---------------- tf32 tensor-core GEMM: C = epilogue(A@B) ----------------
// BM=128, BN=128, BK=32; 8 warps in 2x4; warp tile 64x32; mma m16n8k8.
// mode 0: C = AB (+bias)    mode 1: C = resid + gate*(AB + bias)
// mode 2: C = gelu_tanh(AB + bias)
__global__ __launch_bounds__(256) void mma_gemm_kernel(
    const float* __restrict__ A, const float* __restrict__ B, float* __restrict__ C,
    int M, int N, int K,
    const float* __restrict__ bias, const float* __restrict__ resid,
    int gidx, int mode) {
    __shared__ unsigned As[128][36];   // row-major, pad 4 -> conflict-free frag loads
    __shared__ unsigned Bs[32][136];   // k-major,   pad 8 -> conflict-free frag loads

    int tid = threadIdx.x;
    int lane = tid & 31, warp = tid >> 5;
    int wm = warp >> 2, wn = warp & 3;          // 2 x 4 warp grid
    int g = lane >> 2, tg = lane & 3;
    int row0 = blockIdx.y * 128, col0 = blockIdx.x * 128;

    float acc[16][4];                            // [mt*4+nt][4]
#pragma unroll
    for (int i = 0; i < 16; i++)
#pragma unroll
        for (int j = 0; j < 4; j++) acc[i][j] = 0.0f;

    for (int k0 = 0; k0 < K; k0 += 32) {
        // A tile: 128 x 32 floats = 1024 float4 slots
#pragma unroll
        for (int i = 0; i < 4; i++) {
            int idx = tid + i * 256;
            int r = idx >> 3, c4 = (idx & 7) << 2;
            float4 v = *(const float4*)&A[(size_t)(row0 + r) * K + k0 + c4];
            As[r][c4 + 0] = f2tf(v.x); As[r][c4 + 1] = f2tf(v.y);
            As[r][c4 + 2] = f2tf(v.z); As[r][c4 + 3] = f2tf(v.w);
        }
        // B tile: 32 x 128
#pragma unroll
        for (int i = 0; i < 4; i++) {
            int idx = tid + i * 256;
            int r = idx >> 5, c4 = (idx & 31) << 2;
            float4 v = *(const float4*)&B[(size_t)(k0 + r) * N + col0 + c4];
            Bs[r][c4 + 0] = f2tf(v.x); Bs[r][c4 + 1] = f2tf(v.y);
            Bs[r][c4 + 2] = f2tf(v.z); Bs[r][c4 + 3] = f2tf(v.w);
        }
        __syncthreads();
#pragma unroll
        for (int k8 = 0; k8 < 4; k8++) {
            unsigned a[4][4], b[4][2];
#pragma unroll
            for (int mt = 0; mt < 4; mt++) {
                int r = wm * 64 + mt * 16;
                a[mt][0] = As[r + g][k8 * 8 + tg];
                a[mt][1] = As[r + 8 + g][k8 * 8 + tg];
                a[mt][2] = As[r + g][k8 * 8 + tg + 4];
                a[mt][3] = As[r + 8 + g][k8 * 8 + tg + 4];
            }
#pragma unroll
            for (int nt = 0; nt < 4; nt++) {
                int c = wn * 32 + nt * 8 + g;
                b[nt][0] = Bs[k8 * 8 + tg][c];
                b[nt][1] = Bs[k8 * 8 + tg + 4][c];
            }
#pragma unroll
            for (int mt = 0; mt < 4; mt++)
#pragma unroll
                for (int nt = 0; nt < 4; nt++)
                    mma_tf32(acc[mt * 4 + nt], a[mt], b[nt]);
        }
        __syncthreads();
    }

    const float* gate = (gidx >= 0) ? (g_mod + gidx * DM) : nullptr;
#pragma unroll
    for (int mt = 0; mt < 4; mt++) {
#pragma unroll
        for (int nt = 0; nt < 4; nt++) {
            int c = col0 + wn * 32 + nt * 8 + 2 * tg;
#pragma unroll
            for (int half = 0; half < 2; half++) {
                int r = row0 + wm * 64 + mt * 16 + g + half * 8;
#pragma unroll
                for (int jj = 0; jj < 2; jj++) {
                    int cc = c + jj;
                    float v = acc[mt * 4 + nt][half * 2 + jj];
                    if (bias) v += bias[cc];
                    if (mode == 1) {
                        v = resid[(size_t)r * N + cc] + gate[cc] * v;
                    } else if (mode == 2) {
                        float t = v;
                        v = 0.5f * t * (1.0f + tanhf(0.7978845608f * (t + 0.044715f * t * t * t)));
                    }
                    C[(size_t)r * N + cc] = v;
                }
            }
        }
    }
}

// ---------------- qkv post: rmsnorm(q,k) + rope, scatter to [h][l][dh] ----------------
__global__ void qkv_post_kernel(const float* __restrict__ pe,
                                const float* __restrict__ oqs, const float* __restrict__ oks,
                                const float* __restrict__ cqs, const float* __restrict__ cks) {
    int gl = blockIdx.x;      // global token (cond first)
    int h = blockIdx.y;
    int d = threadIdx.x;      // 0..63
    bool is_cond = gl < LC;
    const float* src = is_cond ? (g_qkv + (size_t)LO * 3 * DM + (size_t)gl * 3 * DM)
                               : (g_qkv + (size_t)(gl - LC) * 3 * DM);
    const float* qs = is_cond ? cqs : oqs;
    const float* ks = is_cond ? cks : oks;
    float qv = src[h * DH + d];
    float kv = src[DM + h * DH + d];
    float vv = src[2 * DM + h * DH + d];
    float qss = qv * qv, kss = kv * kv;
#pragma unroll
    for (int off = 16; off > 0; off >>= 1) {
        qss += __shfl_xor_sync(0xffffffffu, qss, off);
        kss += __shfl_xor_sync(0xffffffffu, kss, off);
    }
    __shared__ float red[4];
    int w = d >> 5;
    if ((d & 31) == 0) { red[w] = qss; red[2 + w] = kss; }
    __syncthreads();
    qss = red[0] + red[1];
    kss = red[2] + red[3];
    float qn = qv * rsqrtf(qss * (1.0f / DH) + 1e-6f) * qs[d];
    float kn = kv * rsqrtf(kss * (1.0f / DH) + 1e-6f) * ks[d];
    __shared__ float sq[DH], sk[DH];
    sq[d] = qn; sk[d] = kn;
    __syncthreads();
    int p = d >> 1, j = d & 1;
    const float* pp = pe + (((size_t)gl * 32 + p) * 2 + j) * 2;
    float q0 = sq[2 * p], q1 = sq[2 * p + 1];
    float k0 = sk[2 * p], k1 = sk[2 * p + 1];
    float qo = pp[0] * q0 + pp[1] * q1;
    float ko = pp[0] * k0 + pp[1] * k1;
    size_t oidx = ((size_t)h * LT + gl) * DH + d;
    g_q[oidx] = qo;
    g_k[oidx] = ko;
    g_v[oidx] = vv;
}

// ---------------- attention: flash, 128 q-rows/block, 64-key tiles ----------------
// 256 threads = 16(tx: cols) x 16(ty: rows); thread tile 8 rows x 4 cols.
#define QP 68   // padded row stride (floats)
__global__ __launch_bounds__(256) void attn_kernel() {
    extern __shared__ float sm[];
    float* Qs = sm;                       // [128][QP]
    float* Ks = Qs + 128 * QP;            // [64][QP]
    float* Vs = Ks + 64 * QP;             // [64][QP]
    float* Ps = Vs + 64 * QP;             // [128][QP]
    float* row_m = Ps + 128 * QP;         // [128]
    float* row_l = row_m + 128;           // [128]
    float* corr_s = row_l + 128;          // [128]

    int h = blockIdx.x;
    int q0 = blockIdx.y * 128;
    int tid = threadIdx.x;
    int tx = tid & 15, ty = tid >> 4;

    const float* qb = g_q + ((size_t)h * LT + q0) * DH;
    const float* kb = g_k + (size_t)h * LT * DH;
    const float* vb = g_v + (size_t)h * LT * DH;

    // load Q tile (scaled)
#pragma unroll
    for (int i = 0; i < 8; i++) {
        int idx = tid + i * 256;          // 2048 float4 slots
        int r = idx >> 4, c4 = (idx & 15) << 2;
        float4 v = *(const float4*)&qb[(size_t)r * DH + c4];
        float* d = &Qs[r * QP + c4];
        d[0] = v.x * 0.125f; d[1] = v.y * 0.125f;
        d[2] = v.z * 0.125f; d[3] = v.w * 0.125f;
    }
    if (tid < 128) { row_m[tid] = -3e38f; row_l[tid] = 0.0f; }

    float o[8][4];
#pragma unroll
    for (int i = 0; i < 8; i++)
#pragma unroll
        for (int j = 0; j < 4; j++) o[i][j] = 0.0f;

    for (int kt = 0; kt < LT; kt += 64) {
        __syncthreads();   // prior PV reads of Ks/Vs/Ps done
        // load K,V tiles: 64x64 each = 1024 float4 slots each
#pragma unroll
        for (int i = 0; i < 4; i++) {
            int idx = tid + i * 256;
            int r = idx >> 4, c4 = (idx & 15) << 2;
            *(float4*)&Ks[r * QP + c4] = *(const float4*)&kb[(size_t)(kt + r) * DH + c4];
            *(float4*)&Vs[r * QP + c4] = *(const float4*)&vb[(size_t)(kt + r) * DH + c4];
        }
        __syncthreads();

        // S = Q K^T  (8x4 per thread)
        float s[8][4];
#pragma unroll
        for (int i = 0; i < 8; i++)
#pragma unroll
            for (int j = 0; j < 4; j++) s[i][j] = 0.0f;
#pragma unroll
        for (int d = 0; d < DH; d += 4) {
            float4 a4[8], k4[4];
#pragma unroll
            for (int i = 0; i < 8; i++) a4[i] = *(float4*)&Qs[(ty * 8 + i) * QP + d];
#pragma unroll
            for (int j = 0; j < 4; j++) k4[j] = *(float4*)&Ks[(tx * 4 + j) * QP + d];
#pragma unroll
            for (int i = 0; i < 8; i++)
#pragma unroll
                for (int j = 0; j < 4; j++) {
                    s[i][j] += a4[i].x * k4[j].x + a4[i].y * k4[j].y
                             + a4[i].z * k4[j].z + a4[i].w * k4[j].w;
                }
        }
        // store S tile
#pragma unroll
        for (int i = 0; i < 8; i++) {
            float4 v = make_float4(s[i][0], s[i][1], s[i][2], s[i][3]);
            *(float4*)&Ps[(ty * 8 + i) * QP + tx * 4] = v;
        }
        __syncthreads();

        // online softmax: 2 threads per row, 32 cols each
        {
            int r = tid >> 1, half = tid & 1;
            float* prow = &Ps[r * QP + half * 32];
            float mx = -3e38f;
#pragma unroll
            for (int c = 0; c < 32; c++) mx = fmaxf(mx, prow[c]);
            mx = fmaxf(mx, __shfl_xor_sync(0xffffffffu, mx, 1));
            float m_old = row_m[r];
            float m_new = fmaxf(m_old, mx);
            float corr = __expf(m_old - m_new);
            float ls = 0.0f;
#pragma unroll
            for (int c = 0; c < 32; c++) {
                float p = __expf(prow[c] - m_new);
                prow[c] = p;
                ls += p;
            }
            ls += __shfl_xor_sync(0xffffffffu, ls, 1);
            if (half == 0) {
                row_m[r] = m_new;
                row_l[r] = row_l[r] * corr + ls;
                corr_s[r] = corr;
            }
        }
        __syncthreads();

        // O = O*corr + P V
#pragma unroll
        for (int i = 0; i < 8; i++) {
            float cr = corr_s[ty * 8 + i];
#pragma unroll
            for (int j = 0; j < 4; j++) o[i][j] *= cr;
        }
#pragma unroll
        for (int kk = 0; kk < 64; kk += 4) {
            float4 a4[8], b4[4];
#pragma unroll
            for (int i = 0; i < 8; i++) a4[i] = *(float4*)&Ps[(ty * 8 + i) * QP + kk];
#pragma unroll
            for (int q = 0; q < 4; q++) b4[q] = *(float4*)&Vs[(kk + q) * QP + tx * 4];
#pragma unroll
            for (int i = 0; i < 8; i++) {
                o[i][0] += a4[i].x * b4[0].x + a4[i].y * b4[1].x + a4[i].z * b4[2].x + a4[i].w * b4[3].x;
                o[i][1] += a4[i].x * b4[0].y + a4[i].y * b4[1].y + a4[i].z * b4[2].y + a4[i].w * b4[3].y;
                o[i][2] += a4[i].x * b4[0].z + a4[i].y * b4[1].z + a4[i].z * b4[2].z + a4[i].w * b4[3].z;
                o[i][3] += a4[i].x * b4[0].w + a4[i].y * b4[1].w + a4[i].z * b4[2].w + a4[i].w * b4[3].w;
            }
        }
    }
    __syncthreads();
#pragma unroll
    for (int i = 0; i < 8; i++) {
        int r = ty * 8 + i;
        float inv = 1.0f / row_l[r];
        float4 v = make_float4(o[i][0] * inv, o[i][1] * inv, o[i][2] * inv, o[i][3] * inv);
        *(float4*)&g_attn[(size_t)(q0 + r) * DM + h * DH + tx * 4] = v;
    }
}

// ---------------- launch ----------------
extern "C" void kernel_launch(void* const* d_in, const int* in_sizes, int n_in,
                              void* d_out, int out_size) {
    const float* obs   = (const float*)d_in[0];
    const float* cond  = (const float*)d_in[1];
    const float* vec   = (const float*)d_in[2];
    const float* pe    = (const float*)d_in[3];
    const float* o_mod_w = (const float*)d_in[4];
    const float* o_mod_b = (const float*)d_in[5];
    const float* o_qkv_w = (const float*)d_in[6];
    const float* o_q_s   = (const float*)d_in[7];
    const float* o_k_s   = (const float*)d_in[8];
    const float* o_proj_w = (const float*)d_in[9];
    const float* o_proj_b = (const float*)d_in[10];
    const float* o_mlp_w1 = (const float*)d_in[11];
    const float* o_mlp_b1 = (const float*)d_in[12];
    const float* o_mlp_w2 = (const float*)d_in[13];
    const float* o_mlp_b2 = (const float*)d_in[14];
    const float* c_mod_w = (const float*)d_in[15];
    const float* c_mod_b = (const float*)d_in[16];
    const float* c_qkv_w = (const float*)d_in[17];
    const float* c_q_s   = (const float*)d_in[18];
    const float* c_k_s   = (const float*)d_in[19];
    const float* c_proj_w = (const float*)d_in[20];
    const float* c_proj_b = (const float*)d_in[21];
    const float* c_mlp_w1 = (const float*)d_in[22];
    const float* c_mlp_b1 = (const float*)d_in[23];
    const float* c_mlp_w2 = (const float*)d_in[24];
    const float* c_mlp_b2 = (const float*)d_in[25];

    float* out = (float*)d_out;
    float* out_obs = out;                 // rows 0..LO-1
    float* out_cond = out + (size_t)LO * DM;

    float *p_xm, *p_qkv, *p_attn, *p_h;
    cudaGetSymbolAddress((void**)&p_xm, g_xm);
    cudaGetSymbolAddress((void**)&p_qkv, g_qkv);
    cudaGetSymbolAddress((void**)&p_attn, g_attn);
    cudaGetSymbolAddress((void**)&p_h, g_h);

    static int attn_smem = 0;
    if (!attn_smem) {
        attn_smem = (int)(((128 + 64 + 64 + 128) * QP + 3 * 128) * sizeof(float));
        cudaFuncSetAttribute(attn_kernel, cudaFuncAttributeMaxDynamicSharedMemorySize, attn_smem);
    }
    int smem_bytes = (int)(((128 + 64 + 64 + 128) * QP + 3 * 128) * sizeof(float));

    // 1. modulation vectors
    mod_kernel<<<48, 256>>>(vec, o_mod_w, o_mod_b, c_mod_w, c_mod_b);

    // 2. LN + mod (chunks: 0=shift1, 1=scale1)
    ln_mod_kernel<<<LO, 256>>>(obs, p_xm, 0, 0, 1);
    ln_mod_kernel<<<LC, 256>>>(cond, p_xm + (size_t)LO * DM, 1, 0, 1);

    // 3. qkv GEMMs
    {
        dim3 g(3 * DM / 128, LO / 128);
        mma_gemm_kernel<<<g, 256>>>(p_xm, o_qkv_w, p_qkv, LO, 3 * DM, DM, nullptr, nullptr, -1, 0);
    }
    {
        dim3 g(3 * DM / 128, LC / 128);
        mma_gemm_kernel<<<g, 256>>>(p_xm + (size_t)LO * DM, c_qkv_w, p_qkv + (size_t)LO * 3 * DM,
                                    LC, 3 * DM, DM, nullptr, nullptr, -1, 0);
    }

    // 4. rmsnorm + rope + scatter
    {
        dim3 g(LT, NH);
        qkv_post_kernel<<<g, 64>>>(pe, o_q_s, o_k_s, c_q_s, c_k_s);
    }

    // 5. attention
    {
        dim3 g(NH, LT / 128);
        attn_kernel<<<g, 256, smem_bytes>>>();
    }

    // 6. proj + gated residual (gate1 = chunk 2)
    {
        dim3 g(DM / 128, LO / 128);
        mma_gemm_kernel<<<g, 256>>>(p_attn + (size_t)LC * DM, o_proj_w, out_obs,
                                    LO, DM, DM, o_proj_b, obs, 0 * 6 + 2, 1);
    }
    {
        dim3 g(DM / 128, LC / 128);
        mma_gemm_kernel<<<g, 256>>>(p_attn, c_proj_w, out_cond,
                                    LC, DM, DM, c_proj_b, cond, 1 * 6 + 2, 1);
    }

    // 7. LN2 + mod (chunks: 3=shift2, 4=scale2)
    ln_mod_kernel<<<LO, 256>>>(out_obs, p_xm, 0, 3, 4);
    ln_mod_kernel<<<LC, 256>>>(out_cond, p_xm + (size_t)LO * DM, 1, 3, 4);

    // 8. mlp1 + gelu
    {
        dim3 g(MH / 128, LO / 128);
        mma_gemm_kernel<<<g, 256>>>(p_xm, o_mlp_w1, p_h, LO, MH, DM, o_mlp_b1, nullptr, -1, 2);
    }
    {
        dim3 g(MH / 128, LC / 128);
        mma_gemm_kernel<<<g, 256>>>(p_xm + (size_t)LO * DM, c_mlp_w1, p_h + (size_t)LO * MH,
                                    LC, MH, DM, c_mlp_b1, nullptr, -1, 2);
    }

    // 9. mlp2 + gated residual (gate2 = chunk 5), in-place residual on d_out
    {
        dim3 g(DM / 128, LO / 128);
        mma_gemm_kernel<<<g, 256>>>(p_h, o_mlp_w2, out_obs, LO, DM, MH, o_mlp_b2, out_obs, 0 * 6 + 5, 1);
    }
    {
        dim3 g(DM / 128, LC / 128);
        mma_gemm_kernel<<<g, 256>>>(p_h + (size_t)LO * MH, c_mlp_w2, out_cond,
                                    LC, DM, MH, c_mlp_b2, out_cond, 1 * 6 + 5, 1);
    }
}

// round 4
// speedup vs baseline: 3.0198x; 1.8432x over previous
#include <cuda_runtime.h>
#include <cuda_bf16.h>
#include <math.h>

#define LO 3072
#define LC 1024
#define LT 4096   // LO + LC
#define DM 1024   // model dim
#define NH 16
#define DH 64
#define MH 4096

// ---------------- scratch (device globals; no allocation allowed) ----------------
__device__ float g_mod[12 * DM];          // [2 streams][6 chunks][1024]
__device__ float g_xm[LT * DM];           // modulated LN output (obs rows 0..LO-1, cond at LO)
__device__ float g_qkv[LT * 3 * DM];      // raw qkv (obs rows at 0, cond rows at LO*3*DM)
__device__ float g_q[NH * LT * DH];       // [h][global_l][dh], cond tokens first (l<LC)
__device__ float g_k[NH * LT * DH];
__device__ float g_v[NH * LT * DH];
__device__ float g_attn[LT * DM];         // attention out, (L, H*Dh), global l order
__device__ float g_h[LT * MH];            // mlp hidden (obs at 0, cond at LO*MH)

// ---------------- helpers ----------------
__device__ __forceinline__ unsigned f2tf(float f) {
    unsigned u;
    asm("cvt.rna.tf32.f32 %0, %1;" : "=r"(u) : "f"(f));
    return u;
}

__device__ __forceinline__ void mma_tf32(float d[4], const unsigned a[4], const unsigned b[2]) {
    asm volatile(
        "mma.sync.aligned.m16n8k8.row.col.f32.tf32.tf32.f32 "
        "{%0,%1,%2,%3}, {%4,%5,%6,%7}, {%8,%9}, {%0,%1,%2,%3};"
        : "+f"(d[0]), "+f"(d[1]), "+f"(d[2]), "+f"(d[3])
        : "r"(a[0]), "r"(a[1]), "r"(a[2]), "r"(a[3]), "r"(b[0]), "r"(b[1]));
}

// ---------------- modulation: silu(vec) @ mod_w + mod_b ----------------
__global__ void mod_kernel(const float* __restrict__ vec,
                           const float* __restrict__ ow, const float* __restrict__ ob,
                           const float* __restrict__ cw, const float* __restrict__ cb) {
    __shared__ float sv[DM];
    int tid = threadIdx.x;
    for (int i = tid; i < DM; i += 256) {
        float v = vec[i];
        sv[i] = v / (1.0f + expf(-v));
    }
    __syncthreads();
    int j = blockIdx.x * 256 + tid;          // 0 .. 12287
    int stream = j / (6 * DM);
    int jj = j % (6 * DM);
    const float* w = stream ? cw : ow;
    const float* b = stream ? cb : ob;
    float acc = 0.0f;
    for (int i = 0; i < DM; i++)
        acc += sv[i] * w[(size_t)i * (6 * DM) + jj];
    g_mod[stream * 6 * DM + jj] = acc + b[jj];
}

// ---------------- layernorm + modulation: (1+scale)*LN(x) + shift ----------------
__global__ void ln_mod_kernel(const float* __restrict__ x, float* __restrict__ y,
                              int stream, int shiftc, int scalec) {
    int row = blockIdx.x;
    int tid = threadIdx.x;
    const float* xr = x + (size_t)row * DM;
    __shared__ float r1[256], r2[256];
    float s = 0.0f, ss = 0.0f;
    for (int c = tid; c < DM; c += 256) {
        float v = xr[c];
        s += v; ss += v * v;
    }
    r1[tid] = s; r2[tid] = ss;
    __syncthreads();
    for (int st = 128; st > 0; st >>= 1) {
        if (tid < st) { r1[tid] += r1[tid + st]; r2[tid] += r2[tid + st]; }
        __syncthreads();
    }
    float mean = r1[0] * (1.0f / DM);
    float var = r2[0] * (1.0f / DM) - mean * mean;
    float inv = rsqrtf(var + 1e-6f);
    const float* sh = g_mod + (stream * 6 + shiftc) * DM;
    const float* sc = g_mod + (stream * 6 + scalec) * DM;
    float* yr = y + (size_t)row * DM;
    for (int c = tid; c < DM; c += 256) {
        yr[c] = (xr[c] - mean) * inv * (1.0f + sc[c]) + sh[c];
    }
}

// ---------------- tf32 tensor-core GEMM: C = epilogue(A@B) ----------------
// BM=128, BN=128, BK=32; 8 warps in 2x4; warp tile 64x32; mma m16n8k8.
// mode 0: C = AB (+bias)    mode 1: C = resid + gate*(AB + bias)
// mode 2: C = gelu_tanh(AB + bias)
__global__ __launch_bounds__(256) void mma_gemm_kernel(
    const float* __restrict__ A, const float* __restrict__ B, float* __restrict__ C,
    int M, int N, int K,
    const float* __restrict__ bias, const float* __restrict__ resid,
    int gidx, int mode) {
    __shared__ unsigned As[128][36];   // row-major, pad 4 -> conflict-free frag loads
    __shared__ unsigned Bs[32][136];   // k-major,   pad 8 -> conflict-free frag loads

    int tid = threadIdx.x;
    int lane = tid & 31, warp = tid >> 5;
    int wm = warp >> 2, wn = warp & 3;          // 2 x 4 warp grid
    int g = lane >> 2, tg = lane & 3;
    int row0 = blockIdx.y * 128, col0 = blockIdx.x * 128;

    float acc[16][4];                            // [mt*4+nt][4]
#pragma unroll
    for (int i = 0; i < 16; i++)
#pragma unroll
        for (int j = 0; j < 4; j++) acc[i][j] = 0.0f;

    for (int k0 = 0; k0 < K; k0 += 32) {
        // A tile: 128 x 32 floats = 1024 float4 slots
#pragma unroll
        for (int i = 0; i < 4; i++) {
            int idx = tid + i * 256;
            int r = idx >> 3, c4 = (idx & 7) << 2;
            float4 v = *(const float4*)&A[(size_t)(row0 + r) * K + k0 + c4];
            As[r][c4 + 0] = f2tf(v.x); As[r][c4 + 1] = f2tf(v.y);
            As[r][c4 + 2] = f2tf(v.z); As[r][c4 + 3] = f2tf(v.w);
        }
        // B tile: 32 x 128
#pragma unroll
        for (int i = 0; i < 4; i++) {
            int idx = tid + i * 256;
            int r = idx >> 5, c4 = (idx & 31) << 2;
            float4 v = *(const float4*)&B[(size_t)(k0 + r) * N + col0 + c4];
            Bs[r][c4 + 0] = f2tf(v.x); Bs[r][c4 + 1] = f2tf(v.y);
            Bs[r][c4 + 2] = f2tf(v.z); Bs[r][c4 + 3] = f2tf(v.w);
        }
        __syncthreads();
#pragma unroll
        for (int k8 = 0; k8 < 4; k8++) {
            unsigned a[4][4], b[4][2];
#pragma unroll
            for (int mt = 0; mt < 4; mt++) {
                int r = wm * 64 + mt * 16;
                a[mt][0] = As[r + g][k8 * 8 + tg];
                a[mt][1] = As[r + 8 + g][k8 * 8 + tg];
                a[mt][2] = As[r + g][k8 * 8 + tg + 4];
                a[mt][3] = As[r + 8 + g][k8 * 8 + tg + 4];
            }
#pragma unroll
            for (int nt = 0; nt < 4; nt++) {
                int c = wn * 32 + nt * 8 + g;
                b[nt][0] = Bs[k8 * 8 + tg][c];
                b[nt][1] = Bs[k8 * 8 + tg + 4][c];
            }
#pragma unroll
            for (int mt = 0; mt < 4; mt++)
#pragma unroll
                for (int nt = 0; nt < 4; nt++)
                    mma_tf32(acc[mt * 4 + nt], a[mt], b[nt]);
        }
        __syncthreads();
    }

    const float* gate = (gidx >= 0) ? (g_mod + gidx * DM) : nullptr;
#pragma unroll
    for (int mt = 0; mt < 4; mt++) {
#pragma unroll
        for (int nt = 0; nt < 4; nt++) {
            int c = col0 + wn * 32 + nt * 8 + 2 * tg;
#pragma unroll
            for (int half = 0; half < 2; half++) {
                int r = row0 + wm * 64 + mt * 16 + g + half * 8;
#pragma unroll
                for (int jj = 0; jj < 2; jj++) {
                    int cc = c + jj;
                    float v = acc[mt * 4 + nt][half * 2 + jj];
                    if (bias) v += bias[cc];
                    if (mode == 1) {
                        v = resid[(size_t)r * N + cc] + gate[cc] * v;
                    } else if (mode == 2) {
                        float t = v;
                        v = 0.5f * t * (1.0f + tanhf(0.7978845608f * (t + 0.044715f * t * t * t)));
                    }
                    C[(size_t)r * N + cc] = v;
                }
            }
        }
    }
}

// ---------------- qkv post: rmsnorm(q,k) + rope, scatter to [h][l][dh] ----------------
__global__ void qkv_post_kernel(const float* __restrict__ pe,
                                const float* __restrict__ oqs, const float* __restrict__ oks,
                                const float* __restrict__ cqs, const float* __restrict__ cks) {
    int gl = blockIdx.x;      // global token (cond first)
    int h = blockIdx.y;
    int d = threadIdx.x;      // 0..63
    bool is_cond = gl < LC;
    const float* src = is_cond ? (g_qkv + (size_t)LO * 3 * DM + (size_t)gl * 3 * DM)
                               : (g_qkv + (size_t)(gl - LC) * 3 * DM);
    const float* qs = is_cond ? cqs : oqs;
    const float* ks = is_cond ? cks : oks;
    float qv = src[h * DH + d];
    float kv = src[DM + h * DH + d];
    float vv = src[2 * DM + h * DH + d];
    float qss = qv * qv, kss = kv * kv;
#pragma unroll
    for (int off = 16; off > 0; off >>= 1) {
        qss += __shfl_xor_sync(0xffffffffu, qss, off);
        kss += __shfl_xor_sync(0xffffffffu, kss, off);
    }
    __shared__ float red[4];
    int w = d >> 5;
    if ((d & 31) == 0) { red[w] = qss; red[2 + w] = kss; }
    __syncthreads();
    qss = red[0] + red[1];
    kss = red[2] + red[3];
    float qn = qv * rsqrtf(qss * (1.0f / DH) + 1e-6f) * qs[d];
    float kn = kv * rsqrtf(kss * (1.0f / DH) + 1e-6f) * ks[d];
    __shared__ float sq[DH], sk[DH];
    sq[d] = qn; sk[d] = kn;
    __syncthreads();
    int p = d >> 1, j = d & 1;
    const float* pp = pe + (((size_t)gl * 32 + p) * 2 + j) * 2;
    float q0 = sq[2 * p], q1 = sq[2 * p + 1];
    float k0 = sk[2 * p], k1 = sk[2 * p + 1];
    float qo = pp[0] * q0 + pp[1] * q1;
    float ko = pp[0] * k0 + pp[1] * k1;
    size_t oidx = ((size_t)h * LT + gl) * DH + d;
    g_q[oidx] = qo;
    g_k[oidx] = ko;
    g_v[oidx] = vv;
}

// ---------------- attention: flash w/ tf32 mma, 128 q-rows/block, 64-key tiles ----------------
// 8 warps in 4x2 (wm: 32 q-rows each, wn: 32 cols each). mma m16n8k8.
#define AS 68   // padded row stride (u32 words)
__global__ __launch_bounds__(256, 2) void attn_mma_kernel() {
    extern __shared__ unsigned smu[];
    unsigned* Qs = smu;                    // [128][AS] tf32
    unsigned* Ks = Qs + 128 * AS;          // [64][AS]  tf32
    unsigned* Vs = Ks + 64 * AS;           // [64][AS]  tf32
    float* Ps = (float*)(Vs + 64 * AS);    // [128][AS] fp32 scores
    float* row_m = Ps + 128 * AS;          // [128]
    float* row_l = row_m + 128;            // [128]
    float* corr_s = row_l + 128;           // [128]

    int h = blockIdx.x;
    int q0 = blockIdx.y * 128;
    int tid = threadIdx.x;
    int lane = tid & 31, warp = tid >> 5;
    int wm = warp >> 1, wn = warp & 1;     // 4 x 2
    int g = lane >> 2, tg = lane & 3;

    const float* qb = g_q + ((size_t)h * LT + q0) * DH;
    const float* kb = g_k + (size_t)h * LT * DH;
    const float* vb = g_v + (size_t)h * LT * DH;

    // load Q tile (scaled, tf32)
#pragma unroll
    for (int i = 0; i < 8; i++) {
        int idx = tid + i * 256;           // 2048 float4 slots
        int r = idx >> 4, c4 = (idx & 15) << 2;
        float4 v = *(const float4*)&qb[(size_t)r * DH + c4];
        unsigned* d = &Qs[r * AS + c4];
        d[0] = f2tf(v.x * 0.125f); d[1] = f2tf(v.y * 0.125f);
        d[2] = f2tf(v.z * 0.125f); d[3] = f2tf(v.w * 0.125f);
    }
    if (tid < 128) { row_m[tid] = -3e38f; row_l[tid] = 0.0f; }

    float acc_o[2][4][4];
#pragma unroll
    for (int mt = 0; mt < 2; mt++)
#pragma unroll
        for (int nt = 0; nt < 4; nt++)
#pragma unroll
            for (int j = 0; j < 4; j++) acc_o[mt][nt][j] = 0.0f;

    for (int kt = 0; kt < LT; kt += 64) {
        __syncthreads();   // prior iteration's PV reads of Vs/Ps done
        // load K,V tiles (tf32): 64x64 each = 1024 float4 slots each
#pragma unroll
        for (int i = 0; i < 4; i++) {
            int idx = tid + i * 256;
            int r = idx >> 4, c4 = (idx & 15) << 2;
            float4 k4 = *(const float4*)&kb[(size_t)(kt + r) * DH + c4];
            float4 v4 = *(const float4*)&vb[(size_t)(kt + r) * DH + c4];
            unsigned* dk = &Ks[r * AS + c4];
            dk[0] = f2tf(k4.x); dk[1] = f2tf(k4.y); dk[2] = f2tf(k4.z); dk[3] = f2tf(k4.w);
            unsigned* dv = &Vs[r * AS + c4];
            dv[0] = f2tf(v4.x); dv[1] = f2tf(v4.y); dv[2] = f2tf(v4.z); dv[3] = f2tf(v4.w);
        }
        __syncthreads();

        // ---- S = Q K^T : warp computes 32x32 ----
        float acc_s[2][4][4];
#pragma unroll
        for (int mt = 0; mt < 2; mt++)
#pragma unroll
            for (int nt = 0; nt < 4; nt++)
#pragma unroll
                for (int j = 0; j < 4; j++) acc_s[mt][nt][j] = 0.0f;
#pragma unroll
        for (int k8 = 0; k8 < 8; k8++) {
            unsigned a[2][4], b[4][2];
#pragma unroll
            for (int mt = 0; mt < 2; mt++) {
                int r = wm * 32 + mt * 16;
                a[mt][0] = Qs[(r + g) * AS + k8 * 8 + tg];
                a[mt][1] = Qs[(r + 8 + g) * AS + k8 * 8 + tg];
                a[mt][2] = Qs[(r + g) * AS + k8 * 8 + tg + 4];
                a[mt][3] = Qs[(r + 8 + g) * AS + k8 * 8 + tg + 4];
            }
#pragma unroll
            for (int nt = 0; nt < 4; nt++) {
                int c = wn * 32 + nt * 8 + g;
                b[nt][0] = Ks[c * AS + k8 * 8 + tg];
                b[nt][1] = Ks[c * AS + k8 * 8 + tg + 4];
            }
#pragma unroll
            for (int mt = 0; mt < 2; mt++)
#pragma unroll
                for (int nt = 0; nt < 4; nt++)
                    mma_tf32(acc_s[mt][nt], a[mt], b[nt]);
        }
        // scatter S -> Ps (fp32)
#pragma unroll
        for (int mt = 0; mt < 2; mt++)
#pragma unroll
            for (int nt = 0; nt < 4; nt++)
#pragma unroll
                for (int half = 0; half < 2; half++) {
                    int r = wm * 32 + mt * 16 + half * 8 + g;
                    int c = wn * 32 + nt * 8 + 2 * tg;
                    Ps[r * AS + c]     = acc_s[mt][nt][half * 2 + 0];
                    Ps[r * AS + c + 1] = acc_s[mt][nt][half * 2 + 1];
                }
        __syncthreads();

        // ---- online softmax: 2 threads per row, 32 cols each ----
        {
            int r = tid >> 1, halfc = tid & 1;
            float* prow = &Ps[r * AS + halfc * 32];
            float mx = -3e38f;
#pragma unroll
            for (int c = 0; c < 32; c++) mx = fmaxf(mx, prow[c]);
            mx = fmaxf(mx, __shfl_xor_sync(0xffffffffu, mx, 1));
            float m_old = row_m[r];
            float m_new = fmaxf(m_old, mx);
            float corr = __expf(m_old - m_new);
            float ls = 0.0f;
#pragma unroll
            for (int c = 0; c < 32; c++) {
                float p = __expf(prow[c] - m_new);
                prow[c] = p;
                ls += p;
            }
            ls += __shfl_xor_sync(0xffffffffu, ls, 1);
            if (halfc == 0) {
                row_m[r] = m_new;
                row_l[r] = row_l[r] * corr + ls;
                corr_s[r] = corr;
            }
        }
        __syncthreads();

        // ---- rescale O, then O += P V ----
#pragma unroll
        for (int mt = 0; mt < 2; mt++)
#pragma unroll
            for (int half = 0; half < 2; half++) {
                float cr = corr_s[wm * 32 + mt * 16 + half * 8 + g];
#pragma unroll
                for (int nt = 0; nt < 4; nt++) {
                    acc_o[mt][nt][half * 2 + 0] *= cr;
                    acc_o[mt][nt][half * 2 + 1] *= cr;
                }
            }
#pragma unroll
        for (int k8 = 0; k8 < 8; k8++) {
            unsigned a[2][4], b[4][2];
#pragma unroll
            for (int mt = 0; mt < 2; mt++) {
                int r = wm * 32 + mt * 16;
                a[mt][0] = f2tf(Ps[(r + g) * AS + k8 * 8 + tg]);
                a[mt][1] = f2tf(Ps[(r + 8 + g) * AS + k8 * 8 + tg]);
                a[mt][2] = f2tf(Ps[(r + g) * AS + k8 * 8 + tg + 4]);
                a[mt][3] = f2tf(Ps[(r + 8 + g) * AS + k8 * 8 + tg + 4]);
            }
#pragma unroll
            for (int nt = 0; nt < 4; nt++) {
                int c = wn * 32 + nt * 8 + g;          // output col (d)
                b[nt][0] = Vs[(k8 * 8 + tg) * AS + c];
                b[nt][1] = Vs[(k8 * 8 + tg + 4) * AS + c];
            }
#pragma unroll
            for (int mt = 0; mt < 2; mt++)
#pragma unroll
                for (int nt = 0; nt < 4; nt++)
                    mma_tf32(acc_o[mt][nt], a[mt], b[nt]);
        }
    }
    __syncthreads();

    // epilogue: normalize by row_l, write out
#pragma unroll
    for (int mt = 0; mt < 2; mt++)
#pragma unroll
        for (int half = 0; half < 2; half++) {
            int r = wm * 32 + mt * 16 + half * 8 + g;
            float inv = 1.0f / row_l[r];
#pragma unroll
            for (int nt = 0; nt < 4; nt++) {
                int c = wn * 32 + nt * 8 + 2 * tg;
                float* dst = &g_attn[(size_t)(q0 + r) * DM + h * DH + c];
                dst[0] = acc_o[mt][nt][half * 2 + 0] * inv;
                dst[1] = acc_o[mt][nt][half * 2 + 1] * inv;
            }
        }
}

// ---------------- launch ----------------
extern "C" void kernel_launch(void* const* d_in, const int* in_sizes, int n_in,
                              void* d_out, int out_size) {
    const float* obs   = (const float*)d_in[0];
    const float* cond  = (const float*)d_in[1];
    const float* vec   = (const float*)d_in[2];
    const float* pe    = (const float*)d_in[3];
    const float* o_mod_w = (const float*)d_in[4];
    const float* o_mod_b = (const float*)d_in[5];
    const float* o_qkv_w = (const float*)d_in[6];
    const float* o_q_s   = (const float*)d_in[7];
    const float* o_k_s   = (const float*)d_in[8];
    const float* o_proj_w = (const float*)d_in[9];
    const float* o_proj_b = (const float*)d_in[10];
    const float* o_mlp_w1 = (const float*)d_in[11];
    const float* o_mlp_b1 = (const float*)d_in[12];
    const float* o_mlp_w2 = (const float*)d_in[13];
    const float* o_mlp_b2 = (const float*)d_in[14];
    const float* c_mod_w = (const float*)d_in[15];
    const float* c_mod_b = (const float*)d_in[16];
    const float* c_qkv_w = (const float*)d_in[17];
    const float* c_q_s   = (const float*)d_in[18];
    const float* c_k_s   = (const float*)d_in[19];
    const float* c_proj_w = (const float*)d_in[20];
    const float* c_proj_b = (const float*)d_in[21];
    const float* c_mlp_w1 = (const float*)d_in[22];
    const float* c_mlp_b1 = (const float*)d_in[23];
    const float* c_mlp_w2 = (const float*)d_in[24];
    const float* c_mlp_b2 = (const float*)d_in[25];

    float* out = (float*)d_out;
    float* out_obs = out;                 // rows 0..LO-1
    float* out_cond = out + (size_t)LO * DM;

    float *p_xm, *p_qkv, *p_attn, *p_h;
    cudaGetSymbolAddress((void**)&p_xm, g_xm);
    cudaGetSymbolAddress((void**)&p_qkv, g_qkv);
    cudaGetSymbolAddress((void**)&p_attn, g_attn);
    cudaGetSymbolAddress((void**)&p_h, g_h);

    int smem_bytes = (int)((384 * AS) * 4 + 3 * 128 * 4);
    static int init = 0;
    if (!init) {
        init = 1;
        cudaFuncSetAttribute(attn_mma_kernel, cudaFuncAttributeMaxDynamicSharedMemorySize, smem_bytes);
    }

    // 1. modulation vectors
    mod_kernel<<<48, 256>>>(vec, o_mod_w, o_mod_b, c_mod_w, c_mod_b);

    // 2. LN + mod (chunks: 0=shift1, 1=scale1)
    ln_mod_kernel<<<LO, 256>>>(obs, p_xm, 0, 0, 1);
    ln_mod_kernel<<<LC, 256>>>(cond, p_xm + (size_t)LO * DM, 1, 0, 1);

    // 3. qkv GEMMs
    {
        dim3 g(3 * DM / 128, LO / 128);
        mma_gemm_kernel<<<g, 256>>>(p_xm, o_qkv_w, p_qkv, LO, 3 * DM, DM, nullptr, nullptr, -1, 0);
    }
    {
        dim3 g(3 * DM / 128, LC / 128);
        mma_gemm_kernel<<<g, 256>>>(p_xm + (size_t)LO * DM, c_qkv_w, p_qkv + (size_t)LO * 3 * DM,
                                    LC, 3 * DM, DM, nullptr, nullptr, -1, 0);
    }

    // 4. rmsnorm + rope + scatter
    {
        dim3 g(LT, NH);
        qkv_post_kernel<<<g, 64>>>(pe, o_q_s, o_k_s, c_q_s, c_k_s);
    }

    // 5. attention (tensor-core flash)
    {
        dim3 g(NH, LT / 128);
        attn_mma_kernel<<<g, 256, smem_bytes>>>();
    }

    // 6. proj + gated residual (gate1 = chunk 2)
    {
        dim3 g(DM / 128, LO / 128);
        mma_gemm_kernel<<<g, 256>>>(p_attn + (size_t)LC * DM, o_proj_w, out_obs,
                                    LO, DM, DM, o_proj_b, obs, 0 * 6 + 2, 1);
    }
    {
        dim3 g(DM / 128, LC / 128);
        mma_gemm_kernel<<<g, 256>>>(p_attn, c_proj_w, out_cond,
                                    LC, DM, DM, c_proj_b, cond, 1 * 6 + 2, 1);
    }

    // 7. LN2 + mod (chunks: 3=shift2, 4=scale2)
    ln_mod_kernel<<<LO, 256>>>(out_obs, p_xm, 0, 3, 4);
    ln_mod_kernel<<<LC, 256>>>(out_cond, p_xm + (size_t)LO * DM, 1, 3, 4);

    // 8. mlp1 + gelu
    {
        dim3 g(MH / 128, LO / 128);
        mma_gemm_kernel<<<g, 256>>>(p_xm, o_mlp_w1, p_h, LO, MH, DM, o_mlp_b1, nullptr, -1, 2);
    }
    {
        dim3 g(MH / 128, LC / 128);
        mma_gemm_kernel<<<g, 256>>>(p_xm + (size_t)LO * DM, c_mlp_w1, p_h + (size_t)LO * MH,
                                    LC, MH, DM, c_mlp_b1, nullptr, -1, 2);
    }

    // 9. mlp2 + gated residual (gate2 = chunk 5), in-place residual on d_out
    {
        dim3 g(DM / 128, LO / 128);
        mma_gemm_kernel<<<g, 256>>>(p_h, o_mlp_w2, out_obs, LO, DM, MH, o_mlp_b2, out_obs, 0 * 6 + 5, 1);
    }
    {
        dim3 g(DM / 128, LC / 128);
        mma_gemm_kernel<<<g, 256>>>(p_h + (size_t)LO * MH, c_mlp_w2, out_cond,
                                    LC, DM, MH, c_mlp_b2, out_cond, 1 * 6 + 5, 1);
    }
}